// round 2
// baseline (speedup 1.0000x reference)
#include <cuda_runtime.h>
#include <cstdint>
#include <math.h>

// Problem constants
#define B_      8192
#define ZD_     256
#define CD_     256
#define NSTEPS  32
#define H_      512
#define SZ      (B_*ZD_)      // 2097152
#define SZH     (B_*H_)       // 4194304
#define DT_     0.03125f
#define SQRTDT_ 0.17677669529663687f

// ---------------- device scratch (allocation-free rule: __device__ globals) ---
__device__ float g_C  [SZH];   // ctx@W1_ctx + b1
__device__ float g_ZW [SZH];   // z @ W1_z
__device__ float g_ctl[SZ];    // control output
__device__ float g_z  [SZ];    // z_prev
__device__ float g_zn [SZ];    // z_next
__device__ float g_lw [SZ];    // per-element log_w
__device__ double g_part[2048];

// ---------------- threefry2x32 ------------------------------------------------
__host__ __device__ __forceinline__ void threefry2x32(
    uint32_t ks0, uint32_t ks1, uint32_t x0, uint32_t x1,
    uint32_t& o0, uint32_t& o1)
{
    uint32_t ks2 = ks0 ^ ks1 ^ 0x1BD11BDAu;
    x0 += ks0; x1 += ks1;
#define TF_R(r) { x0 += x1; x1 = (x1 << (r)) | (x1 >> (32-(r))); x1 ^= x0; }
    TF_R(13) TF_R(15) TF_R(26) TF_R(6)   x0 += ks1; x1 += ks2 + 1u;
    TF_R(17) TF_R(29) TF_R(16) TF_R(24)  x0 += ks2; x1 += ks0 + 2u;
    TF_R(13) TF_R(15) TF_R(26) TF_R(6)   x0 += ks0; x1 += ks1 + 3u;
    TF_R(17) TF_R(29) TF_R(16) TF_R(24)  x0 += ks1; x1 += ks2 + 4u;
    TF_R(13) TF_R(15) TF_R(26) TF_R(6)   x0 += ks2; x1 += ks0 + 5u;
#undef TF_R
    o0 = x0; o1 = x1;
}

// XLA ErfInv32 (Giles polynomial) — matches jax erf_inv lowering
__device__ __forceinline__ float erfinv_xla(float x)
{
    float w = -log1pf(-x * x);
    float p;
    if (w < 5.0f) {
        w -= 2.5f;
        p = 2.81022636e-08f;
        p = fmaf(p, w, 3.43273939e-07f);
        p = fmaf(p, w, -3.5233877e-06f);
        p = fmaf(p, w, -4.39150654e-06f);
        p = fmaf(p, w, 0.00021858087f);
        p = fmaf(p, w, -0.00125372503f);
        p = fmaf(p, w, -0.00417768164f);
        p = fmaf(p, w, 0.246640727f);
        p = fmaf(p, w, 1.50140941f);
    } else {
        w = sqrtf(w) - 3.0f;
        p = -0.000200214257f;
        p = fmaf(p, w, 0.000100950558f);
        p = fmaf(p, w, 0.00134934322f);
        p = fmaf(p, w, -0.00367342844f);
        p = fmaf(p, w, 0.00573950773f);
        p = fmaf(p, w, -0.0076224613f);
        p = fmaf(p, w, 0.00943887047f);
        p = fmaf(p, w, 1.00167406f);
        p = fmaf(p, w, 2.83297682f);
    }
    return p * x;
}

// partitionable random_bits -> jax.random.normal element. ctr = flat index (<2^32)
__device__ __forceinline__ float rng_normal(uint32_t kx, uint32_t ky, uint32_t ctr)
{
    uint32_t a, b;
    threefry2x32(kx, ky, 0u, ctr, a, b);   // hi(iota64)=0, lo=ctr
    uint32_t bits = a ^ b;
    float f = __uint_as_float((bits >> 9) | 0x3F800000u) - 1.0f;   // [0,1)
    const float lo = __uint_as_float(0xBF7FFFFFu);                  // nextafter(-1,0)
    float u = fmaxf(lo, fmaf(f, 2.0f, lo));                         // (hi-lo) rounds to 2.0f
    return 1.4142135623730951f * erfinv_xla(u);
}

// ---------------- GEMM: D = op(A) @ B (+bias). 128x64 tile, BK=16, 256 thr ----
// FUSED: op(A)[m,k] = tanhf(A[m,k] + C[m,k] + tscalar*wt[k])
template<bool FUSED>
__global__ __launch_bounds__(256)
void k_gemm(const float* __restrict__ A, const float* __restrict__ C2,
            const float* __restrict__ wt, float tscalar,
            const float* __restrict__ Bw, const float* __restrict__ bias,
            float* __restrict__ D, int M, int Nn, int K)
{
    __shared__ __align__(16) float As[16][132];
    __shared__ __align__(16) float Bs[16][64];
    const int bm = blockIdx.y * 128;
    const int bn = blockIdx.x * 64;
    const int tid = threadIdx.x;
    const int tx = tid & 15, ty = tid >> 4;

    float acc[8][4];
#pragma unroll
    for (int i = 0; i < 8; i++)
#pragma unroll
        for (int j = 0; j < 4; j++) acc[i][j] = 0.f;

    const int lr  = tid >> 1;        // A-load row 0..127
    const int lc  = (tid & 1) * 8;   // A-load col group 0/8
    const int bkr = tid >> 4;        // B-load row 0..15
    const int bkc = (tid & 15) * 4;  // B-load col 0..60

    for (int k0 = 0; k0 < K; k0 += 16) {
        const float* ap = A + (size_t)(bm + lr) * K + k0 + lc;
        float4 a0 = *reinterpret_cast<const float4*>(ap);
        float4 a1 = *reinterpret_cast<const float4*>(ap + 4);
        float va[8] = {a0.x,a0.y,a0.z,a0.w,a1.x,a1.y,a1.z,a1.w};
        if (FUSED) {
            const float* cp = C2 + (size_t)(bm + lr) * K + k0 + lc;
            float4 c0 = *reinterpret_cast<const float4*>(cp);
            float4 c1 = *reinterpret_cast<const float4*>(cp + 4);
            float vc[8] = {c0.x,c0.y,c0.z,c0.w,c1.x,c1.y,c1.z,c1.w};
#pragma unroll
            for (int j = 0; j < 8; j++)
                va[j] = tanhf(va[j] + vc[j] + tscalar * __ldg(&wt[k0 + lc + j]));
        }
#pragma unroll
        for (int j = 0; j < 8; j++) As[lc + j][lr] = va[j];

        float4 bv = *reinterpret_cast<const float4*>(Bw + (size_t)(k0 + bkr) * Nn + bn + bkc);
        *reinterpret_cast<float4*>(&Bs[bkr][bkc]) = bv;
        __syncthreads();

#pragma unroll
        for (int kk = 0; kk < 16; ++kk) {
            float4 x0 = *reinterpret_cast<const float4*>(&As[kk][ty * 8]);
            float4 x1 = *reinterpret_cast<const float4*>(&As[kk][ty * 8 + 4]);
            float4 y  = *reinterpret_cast<const float4*>(&Bs[kk][tx * 4]);
            float xa[8] = {x0.x,x0.y,x0.z,x0.w,x1.x,x1.y,x1.z,x1.w};
            float yb[4] = {y.x,y.y,y.z,y.w};
#pragma unroll
            for (int i = 0; i < 8; i++)
#pragma unroll
                for (int j = 0; j < 4; j++)
                    acc[i][j] = fmaf(xa[i], yb[j], acc[i][j]);
        }
        __syncthreads();
    }

    float4 bz = make_float4(0.f, 0.f, 0.f, 0.f);
    if (bias) bz = *reinterpret_cast<const float4*>(bias + bn + tx * 4);
#pragma unroll
    for (int i = 0; i < 8; i++) {
        float4 v = make_float4(acc[i][0] + bz.x, acc[i][1] + bz.y,
                               acc[i][2] + bz.z, acc[i][3] + bz.w);
        *reinterpret_cast<float4*>(D + (size_t)(bm + ty * 8 + i) * Nn + bn + tx * 4) = v;
    }
}

// ---------------- elementwise kernels ----------------------------------------
__global__ void k_init(float* __restrict__ chain, uint32_t kx, uint32_t ky)
{
    int idx = blockIdx.x * 256 + threadIdx.x;
    if (idx >= SZ) return;
    float z0 = rng_normal(kx, ky, (uint32_t)idx);
    g_z[idx] = z0;
    chain[idx] = z0;        // z_chain[0]
    g_lw[idx] = 0.f;
}

__global__ void k_update_f(int t,
                           const float* __restrict__ ss, const float* __restrict__ bsch,
                           const float* __restrict__ mu_T, const float* __restrict__ sigma_T,
                           float* __restrict__ chain, uint32_t kx, uint32_t ky)
{
    int idx = blockIdx.x * 256 + threadIdx.x;
    if (idx >= SZ) return;
    float sig = __ldg(&ss[t]), beta = __ldg(&bsch[t]);
    float z = g_z[idx], cf = g_ctl[idx];
    float m = mu_T[idx], st = sigma_T[idx];
    float iv = 1.0f / (st * st);
    float g = (1.0f - beta) * (-z) + beta * (-(z - m) * iv);
    float mu_f = z + (sig * sig * g + cf) * DT_;
    float s_f = sig * SQRTDT_;
    float e = rng_normal(kx, ky, (uint32_t)(t * SZ + idx));
    float zn = fmaf(s_f, e, mu_f);
    float d = (zn - mu_f) / s_f;
    // log_w -= lp(z_next; mu_f, s_f)   (const dropped, cancels)
    g_lw[idx] += 0.5f * d * d + logf(s_f);
    g_zn[idx] = zn;
    chain[(size_t)(t + 1) * SZ + idx] = zn;
}

__global__ void k_update_b(int t,
                           const float* __restrict__ ss, const float* __restrict__ bsch,
                           const float* __restrict__ mu_T, const float* __restrict__ sigma_T)
{
    int idx = blockIdx.x * 256 + threadIdx.x;
    if (idx >= SZ) return;
    int tb = (t + NSTEPS - 1) & (NSTEPS - 1);
    float sig = __ldg(&ss[tb]), beta = __ldg(&bsch[tb]);
    float zp = g_z[idx], zn = g_zn[idx], cb = g_ctl[idx];
    float m = mu_T[idx], st = sigma_T[idx];
    float iv = 1.0f / (st * st);
    float g = (1.0f - beta) * (-zn) + beta * (-(zn - m) * iv);
    float mu_b = zn + (sig * sig * g - cb) * DT_;
    float s_b = sig * SQRTDT_;
    float d = (zp - mu_b) / s_b;
    // log_w += lp(z_prev; mu_b, s_b)
    g_lw[idx] += -0.5f * d * d - logf(s_b);
    g_z[idx] = zn;   // advance chain state
}

__global__ void k_final(const float* __restrict__ mu_T, const float* __restrict__ sigma_T,
                        const float* __restrict__ chain)
{
    __shared__ double sd[256];
    int gid = blockIdx.x * 256 + threadIdx.x;
    double s = 0.0;
#pragma unroll
    for (int r = 0; r < 4; r++) {
        int idx = r * (SZ / 4) + gid;
        float zT = g_z[idx];
        float z0 = chain[idx];
        float m = mu_T[idx], st = sigma_T[idx];
        float dd = (zT - m) / st;
        float lw = g_lw[idx] + (-0.5f * dd * dd - logf(st) + 0.5f * z0 * z0);
        s += (double)lw;
    }
    sd[threadIdx.x] = s;
    __syncthreads();
    for (int o = 128; o > 0; o >>= 1) {
        if (threadIdx.x < o) sd[threadIdx.x] += sd[threadIdx.x + o];
        __syncthreads();
    }
    if (threadIdx.x == 0) g_part[blockIdx.x] = sd[0];
}

__global__ void k_reduce(float* __restrict__ out)
{
    __shared__ double sd[256];
    double s = 0.0;
    for (int i = threadIdx.x; i < 2048; i += 256) s += g_part[i];
    sd[threadIdx.x] = s;
    __syncthreads();
    for (int o = 128; o > 0; o >>= 1) {
        if (threadIdx.x < o) sd[threadIdx.x] += sd[threadIdx.x + o];
        __syncthreads();
    }
    if (threadIdx.x == 0) out[0] = (float)(sd[0] / (double)B_);  // mean over B, sum over ZD
}

// ---------------- launch ------------------------------------------------------
extern "C" void kernel_launch(void* const* d_in, const int* in_sizes, int n_in,
                              void* d_out, int out_size)
{
    (void)in_sizes; (void)n_in; (void)out_size;
    const float* ctx     = (const float*)d_in[0];
    const float* mu_T    = (const float*)d_in[1];
    const float* sigma_T = (const float*)d_in[2];
    const float* W1      = (const float*)d_in[3];   // (513, 512) row-major
    const float* b1      = (const float*)d_in[4];
    const float* W2      = (const float*)d_in[5];   // (512, 256) row-major
    const float* b2      = (const float*)d_in[6];
    const float* ss      = (const float*)d_in[7];
    const float* bsch    = (const float*)d_in[8];
    float* out   = (float*)d_out;
    float* chain = out + 1;                          // z_chain (33, 8192, 256)

    // key = (0,42); fold-like split: k0 = block(key,(0,0)), k1 = block(key,(0,1))
    uint32_t k0x, k0y, k1x, k1y;
    threefry2x32(0u, 42u, 0u, 0u, k0x, k0y);
    threefry2x32(0u, 42u, 0u, 1u, k1x, k1y);

    static float *pC = nullptr, *pZW, *pctl, *pz, *pzn;
    if (!pC) {
        cudaGetSymbolAddress((void**)&pC,   g_C);
        cudaGetSymbolAddress((void**)&pZW,  g_ZW);
        cudaGetSymbolAddress((void**)&pctl, g_ctl);
        cudaGetSymbolAddress((void**)&pz,   g_z);
        cudaGetSymbolAddress((void**)&pzn,  g_zn);
    }

    const dim3 thr(256);
    const dim3 gG1(H_ / 64, B_ / 128);   // (8,64): K=256 GEMMs -> H
    const dim3 gG2(ZD_ / 64, B_ / 128);  // (4,64): K=512 GEMM  -> ZD
    const int EB = SZ / 256;

    // z0 + logw init
    k_init<<<EB, 256>>>(chain, k0x, k0y);
    // C = ctx @ W1_ctx + b1
    k_gemm<false><<<gG1, thr>>>(ctx, nullptr, nullptr, 0.f, W1 + 256 * H_, b1, pC, B_, H_, CD_);
    // ZW = z0 @ W1_z
    k_gemm<false><<<gG1, thr>>>(pz, nullptr, nullptr, 0.f, W1, nullptr, pZW, B_, H_, ZD_);

    for (int t = 0; t < NSTEPS; t++) {
        float tf = (float)(t + 1) / (float)NSTEPS;
        float tb = (float)t / (float)NSTEPS;
        // c_f = tanh(ZW + C + tf*w1t) @ W2 + b2
        k_gemm<true><<<gG2, thr>>>(pZW, pC, W1 + 512 * H_, tf, W2, b2, pctl, B_, ZD_, H_);
        k_update_f<<<EB, 256>>>(t, ss, bsch, mu_T, sigma_T, chain, k1x, k1y);
        // ZW = z_next @ W1_z   (reused by next step's forward eval)
        k_gemm<false><<<gG1, thr>>>(pzn, nullptr, nullptr, 0.f, W1, nullptr, pZW, B_, H_, ZD_);
        // c_b = tanh(ZW + C + tb*w1t) @ W2 + b2
        k_gemm<true><<<gG2, thr>>>(pZW, pC, W1 + 512 * H_, tb, W2, b2, pctl, B_, ZD_, H_);
        k_update_b<<<EB, 256>>>(t, ss, bsch, mu_T, sigma_T);
    }

    k_final<<<2048, 256>>>(mu_T, sigma_T, chain);
    k_reduce<<<1, 256>>>(out);
}

// round 4
// speedup vs baseline: 2.0327x; 2.0327x over previous
#include <cuda_runtime.h>
#include <cuda_bf16.h>
#include <cstdint>
#include <math.h>

// Problem constants
#define B_      8192
#define ZD_     256
#define CD_     256
#define NSTEPS  32
#define H_      512
#define SZ      (B_*ZD_)      // 2097152
#define SZH     (B_*H_)       // 4194304
#define DT_     0.03125f
#define SQRTDT_ 0.17677669529663687f

// ---------------- device scratch ------------------------------------------------
__device__ float g_C  [SZH];                    // ctx@W1_ctx + b1 (fp32)
__device__ float g_ctl[SZ];                     // control output
__device__ float g_z  [SZ];                     // z_prev (fp32)
__device__ float g_zn [SZ];                     // z_next (fp32)
__device__ float g_lw [SZ];                     // per-element log_w
__device__ double g_part[2048];

// bf16-split operand buffers
__device__ __nv_bfloat16 g_zb_hi[SZ],  g_zb_lo[SZ];     // current z for GEMM1
__device__ __nv_bfloat16 g_ctxb_hi[SZ], g_ctxb_lo[SZ];  // ctx split
__device__ __nv_bfloat16 g_hf_hi[SZH], g_hf_lo[SZH];    // tanh fwd activations
__device__ __nv_bfloat16 g_hb_hi[SZH], g_hb_lo[SZH];    // tanh bwd activations
// transposed + split weights: [N, K] row-major
__device__ __nv_bfloat16 g_w1zt_hi[H_*ZD_], g_w1zt_lo[H_*ZD_];  // [512,256]
__device__ __nv_bfloat16 g_w1ct_hi[H_*CD_], g_w1ct_lo[H_*CD_];  // [512,256]
__device__ __nv_bfloat16 g_w2t_hi[ZD_*H_],  g_w2t_lo[ZD_*H_];   // [256,512]

// ---------------- helpers -------------------------------------------------------
__device__ __forceinline__ uint32_t smem_u32(const void* p) {
    uint32_t a;
    asm("{ .reg .u64 t; cvta.to.shared.u64 t, %1; cvt.u32.u64 %0, t; }" : "=r"(a) : "l"(p));
    return a;
}
__device__ __forceinline__ void ldm_x4(uint32_t* r, uint32_t a) {
    asm volatile("ldmatrix.sync.aligned.m8n8.x4.shared.b16 {%0,%1,%2,%3}, [%4];"
        : "=r"(r[0]), "=r"(r[1]), "=r"(r[2]), "=r"(r[3]) : "r"(a));
}
__device__ __forceinline__ void ldm_x2(uint32_t* r, uint32_t a) {
    asm volatile("ldmatrix.sync.aligned.m8n8.x2.shared.b16 {%0,%1}, [%2];"
        : "=r"(r[0]), "=r"(r[1]) : "r"(a));
}
#define MMA_BF16(acc, a, b) \
    asm volatile("mma.sync.aligned.m16n8k16.row.col.f32.bf16.bf16.f32 " \
        "{%0,%1,%2,%3}, {%4,%5,%6,%7}, {%8,%9}, {%0,%1,%2,%3};" \
        : "+f"((acc)[0]), "+f"((acc)[1]), "+f"((acc)[2]), "+f"((acc)[3]) \
        : "r"((a)[0]), "r"((a)[1]), "r"((a)[2]), "r"((a)[3]), "r"((b)[0]), "r"((b)[1]))

__device__ __forceinline__ void bsplit(float v, __nv_bfloat16& h, __nv_bfloat16& l)
{
    h = __float2bfloat16_rn(v);
    l = __float2bfloat16_rn(v - __bfloat162float(h));
}

// ---------------- threefry2x32 / erfinv / rng ---------------------------------
__host__ __device__ __forceinline__ void threefry2x32(
    uint32_t ks0, uint32_t ks1, uint32_t x0, uint32_t x1,
    uint32_t& o0, uint32_t& o1)
{
    uint32_t ks2 = ks0 ^ ks1 ^ 0x1BD11BDAu;
    x0 += ks0; x1 += ks1;
#define TF_R(r) { x0 += x1; x1 = (x1 << (r)) | (x1 >> (32-(r))); x1 ^= x0; }
    TF_R(13) TF_R(15) TF_R(26) TF_R(6)   x0 += ks1; x1 += ks2 + 1u;
    TF_R(17) TF_R(29) TF_R(16) TF_R(24)  x0 += ks2; x1 += ks0 + 2u;
    TF_R(13) TF_R(15) TF_R(26) TF_R(6)   x0 += ks0; x1 += ks1 + 3u;
    TF_R(17) TF_R(29) TF_R(16) TF_R(24)  x0 += ks1; x1 += ks2 + 4u;
    TF_R(13) TF_R(15) TF_R(26) TF_R(6)   x0 += ks2; x1 += ks0 + 5u;
#undef TF_R
    o0 = x0; o1 = x1;
}

__device__ __forceinline__ float erfinv_xla(float x)
{
    float w = -log1pf(-x * x);
    float p;
    if (w < 5.0f) {
        w -= 2.5f;
        p = 2.81022636e-08f;
        p = fmaf(p, w, 3.43273939e-07f);
        p = fmaf(p, w, -3.5233877e-06f);
        p = fmaf(p, w, -4.39150654e-06f);
        p = fmaf(p, w, 0.00021858087f);
        p = fmaf(p, w, -0.00125372503f);
        p = fmaf(p, w, -0.00417768164f);
        p = fmaf(p, w, 0.246640727f);
        p = fmaf(p, w, 1.50140941f);
    } else {
        w = sqrtf(w) - 3.0f;
        p = -0.000200214257f;
        p = fmaf(p, w, 0.000100950558f);
        p = fmaf(p, w, 0.00134934322f);
        p = fmaf(p, w, -0.00367342844f);
        p = fmaf(p, w, 0.00573950773f);
        p = fmaf(p, w, -0.0076224613f);
        p = fmaf(p, w, 0.00943887047f);
        p = fmaf(p, w, 1.00167406f);
        p = fmaf(p, w, 2.83297682f);
    }
    return p * x;
}

__device__ __forceinline__ float rng_normal(uint32_t kx, uint32_t ky, uint32_t ctr)
{
    uint32_t a, b;
    threefry2x32(kx, ky, 0u, ctr, a, b);
    uint32_t bits = a ^ b;
    float f = __uint_as_float((bits >> 9) | 0x3F800000u) - 1.0f;
    const float lo = __uint_as_float(0xBF7FFFFFu);
    float u = fmaxf(lo, fmaf(f, 2.0f, lo));
    return 1.4142135623730951f * erfinv_xla(u);
}

// ---------------- mma.sync GEMM -------------------------------------------------
// D[128x128] = A[128xK] @ B[128xK]^T via 3-term bf16 emulation (hi*hi+hi*lo+lo*hi).
// EPI==0: out = D + bias  (fp32, [M, Ntot])
// EPI==1: dual tanh epilogue -> 4 bf16 tensors (hf/hb hi+lo), width H_
#define SMEM_BYTES 32768

template<int EPI>
__global__ __launch_bounds__(256)
void k_mma(const __nv_bfloat16* __restrict__ Ahi, const __nv_bfloat16* __restrict__ Alo,
           const __nv_bfloat16* __restrict__ Bhi, const __nv_bfloat16* __restrict__ Blo,
           int K, int Ntot,
           const float* __restrict__ bias, float* __restrict__ Dout,
           const float* __restrict__ Cadd, const float* __restrict__ wt,
           float tf, float tb,
           __nv_bfloat16* __restrict__ hf_hi, __nv_bfloat16* __restrict__ hf_lo,
           __nv_bfloat16* __restrict__ hb_hi, __nv_bfloat16* __restrict__ hb_lo)
{
    extern __shared__ __align__(16) char smem[];
    const uint32_t sb = smem_u32(smem);
    const uint32_t sAH = sb, sAL = sb + 8192, sBH = sb + 16384, sBL = sb + 24576;
    const int tid = threadIdx.x, lane = tid & 31, wid = tid >> 5;
    const int bm = blockIdx.y * 128, bn = blockIdx.x * 128;
    const int wm = (wid & 1) * 64, wn = (wid >> 1) * 32;

    float acc[4][4][4];
#pragma unroll
    for (int mi = 0; mi < 4; mi++)
#pragma unroll
        for (int ni = 0; ni < 4; ni++)
#pragma unroll
            for (int r = 0; r < 4; r++) acc[mi][ni][r] = 0.f;

    // per-thread gmem fetch coords: idx -> (row r, element col ce)
    const int r0i  = tid >> 2;                 // idx0 = tid
    const int ce0  = (tid & 3) * 8;
    const int r1i  = (tid + 256) >> 2;         // idx1 = tid + 256
    const int ce1  = ce0;                      // (idx&3) identical
    // smem store offsets (bytes), XOR swizzle on 16B groups
    const uint32_t so0 = (uint32_t)(r0i * 64 + (((tid & 3) << 4) ^ (((r0i >> 1) & 3) << 4)));
    const uint32_t so1 = (uint32_t)(r1i * 64 + (((tid & 3) << 4) ^ (((r1i >> 1) & 3) << 4)));

    uint4 pf[4][2];
    {
        const __nv_bfloat16* g0 = Ahi + (size_t)(bm + r0i) * K + ce0;
        const __nv_bfloat16* g1 = Ahi + (size_t)(bm + r1i) * K + ce1;
        pf[0][0] = *(const uint4*)g0;                       pf[0][1] = *(const uint4*)g1;
        pf[1][0] = *(const uint4*)(Alo + (size_t)(bm + r0i) * K + ce0);
        pf[1][1] = *(const uint4*)(Alo + (size_t)(bm + r1i) * K + ce1);
        pf[2][0] = *(const uint4*)(Bhi + (size_t)(bn + r0i) * K + ce0);
        pf[2][1] = *(const uint4*)(Bhi + (size_t)(bn + r1i) * K + ce1);
        pf[3][0] = *(const uint4*)(Blo + (size_t)(bn + r0i) * K + ce0);
        pf[3][1] = *(const uint4*)(Blo + (size_t)(bn + r1i) * K + ce1);
    }

    const int NIT = K >> 5;
    for (int it = 0; it < NIT; ++it) {
        __syncthreads();
        *(uint4*)(smem +     0 + so0) = pf[0][0];  *(uint4*)(smem +     0 + so1) = pf[0][1];
        *(uint4*)(smem +  8192 + so0) = pf[1][0];  *(uint4*)(smem +  8192 + so1) = pf[1][1];
        *(uint4*)(smem + 16384 + so0) = pf[2][0];  *(uint4*)(smem + 16384 + so1) = pf[2][1];
        *(uint4*)(smem + 24576 + so0) = pf[3][0];  *(uint4*)(smem + 24576 + so1) = pf[3][1];
        __syncthreads();
        if (it + 1 < NIT) {
            const int k0 = (it + 1) << 5;
            pf[0][0] = *(const uint4*)(Ahi + (size_t)(bm + r0i) * K + k0 + ce0);
            pf[0][1] = *(const uint4*)(Ahi + (size_t)(bm + r1i) * K + k0 + ce1);
            pf[1][0] = *(const uint4*)(Alo + (size_t)(bm + r0i) * K + k0 + ce0);
            pf[1][1] = *(const uint4*)(Alo + (size_t)(bm + r1i) * K + k0 + ce1);
            pf[2][0] = *(const uint4*)(Bhi + (size_t)(bn + r0i) * K + k0 + ce0);
            pf[2][1] = *(const uint4*)(Bhi + (size_t)(bn + r1i) * K + k0 + ce1);
            pf[3][0] = *(const uint4*)(Blo + (size_t)(bn + r0i) * K + k0 + ce0);
            pf[3][1] = *(const uint4*)(Blo + (size_t)(bn + r1i) * K + k0 + ce1);
        }
#pragma unroll
        for (int ks = 0; ks < 2; ks++) {
            uint32_t ah[4][4], al[4][4], bh[4][2], bl[4][2];
#pragma unroll
            for (int mi = 0; mi < 4; mi++) {
                const int row = wm + mi * 16 + (lane & 15);
                const uint32_t cb = (uint32_t)((ks << 5) + ((lane >> 4) << 4));
                const uint32_t off = (uint32_t)(row * 64) + (cb ^ (((row >> 1) & 3) << 4));
                ldm_x4(ah[mi], sAH + off);
                ldm_x4(al[mi], sAL + off);
            }
#pragma unroll
            for (int ni = 0; ni < 4; ni++) {
                const int lm = lane & 15;
                const int n = wn + ni * 8 + (lm & 7);
                const uint32_t cb = (uint32_t)((ks << 5) + ((lm >> 3) << 4));
                const uint32_t off = (uint32_t)(n * 64) + (cb ^ (((n >> 1) & 3) << 4));
                ldm_x2(bh[ni], sBH + off);
                ldm_x2(bl[ni], sBL + off);
            }
#pragma unroll
            for (int mi = 0; mi < 4; mi++)
#pragma unroll
                for (int ni = 0; ni < 4; ni++) {
                    MMA_BF16(acc[mi][ni], ah[mi], bh[ni]);
                    MMA_BF16(acc[mi][ni], ah[mi], bl[ni]);
                    MMA_BF16(acc[mi][ni], al[mi], bh[ni]);
                }
        }
    }

    // ---- epilogue (register accumulators) ----
    const int er = lane >> 2;          // row within 8
    const int ec = (lane & 3) * 2;     // col pair base
#pragma unroll
    for (int mi = 0; mi < 4; mi++) {
#pragma unroll
        for (int ni = 0; ni < 4; ni++) {
            const int row = bm + wm + mi * 16 + er;
            const int col = bn + wn + ni * 8 + ec;
            if (EPI == 0) {
                float2 bz = *(const float2*)(bias + col);
                float2 v0 = make_float2(acc[mi][ni][0] + bz.x, acc[mi][ni][1] + bz.y);
                float2 v1 = make_float2(acc[mi][ni][2] + bz.x, acc[mi][ni][3] + bz.y);
                *(float2*)(Dout + (size_t)row * Ntot + col) = v0;
                *(float2*)(Dout + (size_t)(row + 8) * Ntot + col) = v1;
            } else {
                const float w0 = wt[col], w1 = wt[col + 1];
#pragma unroll
                for (int rr = 0; rr < 2; rr++) {
                    const int rw = row + rr * 8;
                    const size_t ro = (size_t)rw * H_ + col;
                    float b0 = acc[mi][ni][rr * 2]     + Cadd[ro];
                    float b1 = acc[mi][ni][rr * 2 + 1] + Cadd[ro + 1];
                    float f0 = tanhf(fmaf(tf, w0, b0));
                    float f1 = tanhf(fmaf(tf, w1, b1));
                    float g0 = tanhf(fmaf(tb, w0, b0));
                    float g1 = tanhf(fmaf(tb, w1, b1));
                    __nv_bfloat16 h0, l0, h1, l1;
                    __nv_bfloat162 p;
                    bsplit(f0, h0, l0); bsplit(f1, h1, l1);
                    p.x = h0; p.y = h1; *(__nv_bfloat162*)(hf_hi + ro) = p;
                    p.x = l0; p.y = l1; *(__nv_bfloat162*)(hf_lo + ro) = p;
                    bsplit(g0, h0, l0); bsplit(g1, h1, l1);
                    p.x = h0; p.y = h1; *(__nv_bfloat162*)(hb_hi + ro) = p;
                    p.x = l0; p.y = l1; *(__nv_bfloat162*)(hb_lo + ro) = p;
                }
            }
        }
    }
}

// ---------------- prep kernels --------------------------------------------------
__global__ void k_split_w(const float* __restrict__ src, int ld, int K, int total,
                          __nv_bfloat16* __restrict__ oh, __nv_bfloat16* __restrict__ ol)
{
    int idx = blockIdx.x * 256 + threadIdx.x;
    if (idx >= total) return;
    int n = idx / K, k = idx - n * K;
    float v = src[(size_t)k * ld + n];
    __nv_bfloat16 h, l; bsplit(v, h, l);
    oh[idx] = h; ol[idx] = l;
}

__global__ void k_split_plain(const float* __restrict__ src, int total,
                              __nv_bfloat16* __restrict__ oh, __nv_bfloat16* __restrict__ ol)
{
    int idx = blockIdx.x * 256 + threadIdx.x;
    if (idx >= total) return;
    __nv_bfloat16 h, l; bsplit(src[idx], h, l);
    oh[idx] = h; ol[idx] = l;
}

// ---------------- elementwise chain kernels ------------------------------------
__global__ void k_init(float* __restrict__ chain, uint32_t kx, uint32_t ky)
{
    int idx = blockIdx.x * 256 + threadIdx.x;
    if (idx >= SZ) return;
    float z0 = rng_normal(kx, ky, (uint32_t)idx);
    g_z[idx] = z0;
    chain[idx] = z0;
    g_lw[idx] = 0.f;
    __nv_bfloat16 h, l; bsplit(z0, h, l);
    g_zb_hi[idx] = h; g_zb_lo[idx] = l;
}

__global__ void k_update_f(int t,
                           const float* __restrict__ ss, const float* __restrict__ bsch,
                           const float* __restrict__ mu_T, const float* __restrict__ sigma_T,
                           float* __restrict__ chain, uint32_t kx, uint32_t ky)
{
    int idx = blockIdx.x * 256 + threadIdx.x;
    if (idx >= SZ) return;
    float sig = __ldg(&ss[t]), beta = __ldg(&bsch[t]);
    float z = g_z[idx], cf = g_ctl[idx];
    float m = mu_T[idx], st = sigma_T[idx];
    float iv = 1.0f / (st * st);
    float g = (1.0f - beta) * (-z) + beta * (-(z - m) * iv);
    float mu_f = z + (sig * sig * g + cf) * DT_;
    float s_f = sig * SQRTDT_;
    float e = rng_normal(kx, ky, (uint32_t)(t * SZ + idx));
    float zn = fmaf(s_f, e, mu_f);
    float d = (zn - mu_f) / s_f;
    g_lw[idx] += 0.5f * d * d + logf(s_f);
    g_zn[idx] = zn;
    chain[(size_t)(t + 1) * SZ + idx] = zn;
    __nv_bfloat16 h, l; bsplit(zn, h, l);
    g_zb_hi[idx] = h; g_zb_lo[idx] = l;
}

__global__ void k_update_b(int t,
                           const float* __restrict__ ss, const float* __restrict__ bsch,
                           const float* __restrict__ mu_T, const float* __restrict__ sigma_T)
{
    int idx = blockIdx.x * 256 + threadIdx.x;
    if (idx >= SZ) return;
    int tb = (t + NSTEPS - 1) & (NSTEPS - 1);
    float sig = __ldg(&ss[tb]), beta = __ldg(&bsch[tb]);
    float zp = g_z[idx], zn = g_zn[idx], cb = g_ctl[idx];
    float m = mu_T[idx], st = sigma_T[idx];
    float iv = 1.0f / (st * st);
    float g = (1.0f - beta) * (-zn) + beta * (-(zn - m) * iv);
    float mu_b = zn + (sig * sig * g - cb) * DT_;
    float s_b = sig * SQRTDT_;
    float d = (zp - mu_b) / s_b;
    g_lw[idx] += -0.5f * d * d - logf(s_b);
    g_z[idx] = zn;
}

__global__ void k_final(const float* __restrict__ mu_T, const float* __restrict__ sigma_T,
                        const float* __restrict__ chain)
{
    __shared__ double sd[256];
    int gid = blockIdx.x * 256 + threadIdx.x;
    double s = 0.0;
#pragma unroll
    for (int r = 0; r < 4; r++) {
        int idx = r * (SZ / 4) + gid;
        float zT = g_z[idx];
        float z0 = chain[idx];
        float m = mu_T[idx], st = sigma_T[idx];
        float dd = (zT - m) / st;
        float lw = g_lw[idx] + (-0.5f * dd * dd - logf(st) + 0.5f * z0 * z0);
        s += (double)lw;
    }
    sd[threadIdx.x] = s;
    __syncthreads();
    for (int o = 128; o > 0; o >>= 1) {
        if (threadIdx.x < o) sd[threadIdx.x] += sd[threadIdx.x + o];
        __syncthreads();
    }
    if (threadIdx.x == 0) g_part[blockIdx.x] = sd[0];
}

__global__ void k_reduce(float* __restrict__ out)
{
    __shared__ double sd[256];
    double s = 0.0;
    for (int i = threadIdx.x; i < 2048; i += 256) s += g_part[i];
    sd[threadIdx.x] = s;
    __syncthreads();
    for (int o = 128; o > 0; o >>= 1) {
        if (threadIdx.x < o) sd[threadIdx.x] += sd[threadIdx.x + o];
        __syncthreads();
    }
    if (threadIdx.x == 0) out[0] = (float)(sd[0] / (double)B_);
}

// ---------------- launch ------------------------------------------------------
extern "C" void kernel_launch(void* const* d_in, const int* in_sizes, int n_in,
                              void* d_out, int out_size)
{
    (void)in_sizes; (void)n_in; (void)out_size;
    const float* ctx     = (const float*)d_in[0];
    const float* mu_T    = (const float*)d_in[1];
    const float* sigma_T = (const float*)d_in[2];
    const float* W1      = (const float*)d_in[3];   // (513, 512)
    const float* b1      = (const float*)d_in[4];
    const float* W2      = (const float*)d_in[5];   // (512, 256)
    const float* b2      = (const float*)d_in[6];
    const float* ss      = (const float*)d_in[7];
    const float* bsch    = (const float*)d_in[8];
    float* out   = (float*)d_out;
    float* chain = out + 1;
    const float* w1t = W1 + 512 * H_;               // t-coefficient row (512 floats)

    uint32_t k0x, k0y, k1x, k1y;
    threefry2x32(0u, 42u, 0u, 0u, k0x, k0y);
    threefry2x32(0u, 42u, 0u, 1u, k1x, k1y);

    struct Ptrs {
        float *C, *ctl, *z, *zn;
        __nv_bfloat16 *zb_h, *zb_l, *cx_h, *cx_l, *hf_h, *hf_l, *hb_h, *hb_l;
        __nv_bfloat16 *w1z_h, *w1z_l, *w1c_h, *w1c_l, *w2_h, *w2_l;
        bool init;
    };
    static Ptrs P = {};
    if (!P.init) {
        cudaGetSymbolAddress((void**)&P.C, g_C);
        cudaGetSymbolAddress((void**)&P.ctl, g_ctl);
        cudaGetSymbolAddress((void**)&P.z, g_z);
        cudaGetSymbolAddress((void**)&P.zn, g_zn);
        cudaGetSymbolAddress((void**)&P.zb_h, g_zb_hi);  cudaGetSymbolAddress((void**)&P.zb_l, g_zb_lo);
        cudaGetSymbolAddress((void**)&P.cx_h, g_ctxb_hi); cudaGetSymbolAddress((void**)&P.cx_l, g_ctxb_lo);
        cudaGetSymbolAddress((void**)&P.hf_h, g_hf_hi);  cudaGetSymbolAddress((void**)&P.hf_l, g_hf_lo);
        cudaGetSymbolAddress((void**)&P.hb_h, g_hb_hi);  cudaGetSymbolAddress((void**)&P.hb_l, g_hb_lo);
        cudaGetSymbolAddress((void**)&P.w1z_h, g_w1zt_hi); cudaGetSymbolAddress((void**)&P.w1z_l, g_w1zt_lo);
        cudaGetSymbolAddress((void**)&P.w1c_h, g_w1ct_hi); cudaGetSymbolAddress((void**)&P.w1c_l, g_w1ct_lo);
        cudaGetSymbolAddress((void**)&P.w2_h, g_w2t_hi);   cudaGetSymbolAddress((void**)&P.w2_l, g_w2t_lo);
        P.init = true;
    }

    const int EB = SZ / 256;
    const dim3 gCTL(ZD_ / 128, B_ / 128);   // (2, 64)
    const dim3 gH(H_ / 128, B_ / 128);      // (4, 64)

    // ---- prologue ----
    k_split_w<<<(H_ * ZD_ + 255) / 256, 256>>>(W1,            H_, ZD_, H_ * ZD_, P.w1z_h, P.w1z_l);
    k_split_w<<<(H_ * CD_ + 255) / 256, 256>>>(W1 + 256 * H_, H_, CD_, H_ * CD_, P.w1c_h, P.w1c_l);
    k_split_w<<<(ZD_ * H_ + 255) / 256, 256>>>(W2,           ZD_, H_, ZD_ * H_,  P.w2_h,  P.w2_l);
    k_split_plain<<<EB, 256>>>(ctx, SZ, P.cx_h, P.cx_l);
    k_init<<<EB, 256>>>(chain, k0x, k0y);
    // C = ctx @ W1_ctx + b1   (EPI0)
    k_mma<0><<<gH, 256, SMEM_BYTES>>>(P.cx_h, P.cx_l, P.w1c_h, P.w1c_l, CD_, H_,
                                      b1, P.C, nullptr, nullptr, 0.f, 0.f,
                                      nullptr, nullptr, nullptr, nullptr);
    // first layer-1 on z0: hf_0 (tf=1/32); hb slot written but unused this step
    k_mma<1><<<gH, 256, SMEM_BYTES>>>(P.zb_h, P.zb_l, P.w1z_h, P.w1z_l, ZD_, H_,
                                      nullptr, nullptr, P.C, w1t,
                                      1.0f / NSTEPS, -1.0f / NSTEPS,
                                      P.hf_h, P.hf_l, P.hb_h, P.hb_l);

    for (int t = 0; t < NSTEPS; t++) {
        // ctl_f = hf @ W2 + b2
        k_mma<0><<<gCTL, 256, SMEM_BYTES>>>(P.hf_h, P.hf_l, P.w2_h, P.w2_l, H_, ZD_,
                                            b2, P.ctl, nullptr, nullptr, 0.f, 0.f,
                                            nullptr, nullptr, nullptr, nullptr);
        k_update_f<<<EB, 256>>>(t, ss, bsch, mu_T, sigma_T, chain, k1x, k1y);
        // layer-1 on z_{t+1}: hf_{t+1} (tf=(t+2)/32), hb_t (tb=t/32)
        k_mma<1><<<gH, 256, SMEM_BYTES>>>(P.zb_h, P.zb_l, P.w1z_h, P.w1z_l, ZD_, H_,
                                          nullptr, nullptr, P.C, w1t,
                                          (float)(t + 2) / NSTEPS, (float)t / NSTEPS,
                                          P.hf_h, P.hf_l, P.hb_h, P.hb_l);
        // ctl_b = hb @ W2 + b2
        k_mma<0><<<gCTL, 256, SMEM_BYTES>>>(P.hb_h, P.hb_l, P.w2_h, P.w2_l, H_, ZD_,
                                            b2, P.ctl, nullptr, nullptr, 0.f, 0.f,
                                            nullptr, nullptr, nullptr, nullptr);
        k_update_b<<<EB, 256>>>(t, ss, bsch, mu_T, sigma_T);
    }

    k_final<<<2048, 256>>>(mu_T, sigma_T, chain);
    k_reduce<<<1, 256>>>(out);
}